// round 1
// baseline (speedup 1.0000x reference)
#include <cuda_runtime.h>

#define NB 2048
#define NN 64
#define DM 512
#define NH 4
#define DK 128
#define TB 16

__device__ float g_Wqf[DM * NH];
__device__ float g_Wkf[DM * NH];
__device__ float g_ctx[NB * NH * DM];

// ---------------------------------------------------------------------------
// K0: fold Wq/Wk with w_map halves -> [512,4] score projections
// ---------------------------------------------------------------------------
__global__ void fold_kernel(const float* __restrict__ Wq,
                            const float* __restrict__ Wk,
                            const float* __restrict__ w_map) {
    int i = blockIdx.x * blockDim.x + threadIdx.x;
    if (i >= DM) return;
    const float* wq = Wq + i * DM;
    const float* wk = Wk + i * DM;
#pragma unroll
    for (int h = 0; h < NH; h++) {
        float sq = 0.f, sk = 0.f;
        const float* wqh = wq + h * DK;
        const float* wkh = wk + h * DK;
#pragma unroll 4
        for (int d = 0; d < DK; d++) {
            sq += wqh[d] * w_map[d];
            sk += wkh[d] * w_map[DK + d];
        }
        g_Wqf[i * NH + h] = sq;
        g_Wkf[i * NH + h] = sk;
    }
}

// ---------------------------------------------------------------------------
// K1: per-batch scores + masked softmax + ctx = attn @ k_in
// grid 2048, block 256
// ---------------------------------------------------------------------------
__global__ void __launch_bounds__(256) attn_kernel(
    const float* __restrict__ src,  const float* __restrict__ srct,
    const float* __restrict__ srcp,
    const float* __restrict__ seq,  const float* __restrict__ seqe,
    const float* __restrict__ seqt, const float* __restrict__ seqp,
    const int*   __restrict__ mask, float* __restrict__ out_attn)
{
    __shared__ float4 s_wkf[DM];        // Wkf[i][0..3]
    __shared__ float4 s_attnT4[NN];     // per-k: score/attn for 4 heads
    __shared__ float4 s_part[DK * NH];  // pass-2 partials [i4][h]
    __shared__ float  s_qp[4][NH];
    __shared__ float  s_qscore[NH];
    float* sc = (float*)s_attnT4;

    int b = blockIdx.x;
    int t = threadIdx.x;

    // load folded Wk (512 float4) into smem
    const float4* gwkf = (const float4*)g_Wkf;
    s_wkf[t]       = gwkf[t];
    s_wkf[t + 256] = gwkf[t + 256];

    // q_score partials (q_in nonzero at [0,128)=src, [256,384)=src_t, [384,512)=src_p)
    if (t < DK) {
        float a  = src[b * DK + t];
        float tt = srct[b * DK + t];
        float pp = srcp[b * DK + t];
        const float4* gwqf = (const float4*)g_Wqf;
        float4 w0 = gwqf[t];
        float4 w1 = gwqf[2 * DK + t];
        float4 w2 = gwqf[3 * DK + t];
        float q0 = a * w0.x + tt * w1.x + pp * w2.x;
        float q1 = a * w0.y + tt * w1.y + pp * w2.y;
        float q2 = a * w0.z + tt * w1.z + pp * w2.z;
        float q3 = a * w0.w + tt * w1.w + pp * w2.w;
#pragma unroll
        for (int o = 16; o > 0; o >>= 1) {
            q0 += __shfl_xor_sync(0xffffffffu, q0, o);
            q1 += __shfl_xor_sync(0xffffffffu, q1, o);
            q2 += __shfl_xor_sync(0xffffffffu, q2, o);
            q3 += __shfl_xor_sync(0xffffffffu, q3, o);
        }
        if ((t & 31) == 0) {
            int w = t >> 5;
            s_qp[w][0] = q0; s_qp[w][1] = q1; s_qp[w][2] = q2; s_qp[w][3] = q3;
        }
    }
    __syncthreads();

    // pass 1: k_score[h][k]; thread = (k, quarter c). Each quarter is exactly one
    // source tensor (k_in = [seq | seq_e | seq_t | seq_p], each 128 wide).
    {
        int k = t >> 2, c = t & 3;
        const float* kin = (c == 0) ? seq : (c == 1) ? seqe : (c == 2) ? seqt : seqp;
        const float4* row = (const float4*)(kin + (size_t)(b * NN + k) * DK);
        float a0 = 0.f, a1 = 0.f, a2 = 0.f, a3 = 0.f;
#pragma unroll 8
        for (int j = 0; j < 32; j++) {
            float4 v = row[j];
            int i = c * DK + j * 4;
            float4 w0 = s_wkf[i], w1 = s_wkf[i + 1], w2 = s_wkf[i + 2], w3 = s_wkf[i + 3];
            a0 += v.x * w0.x + v.y * w1.x + v.z * w2.x + v.w * w3.x;
            a1 += v.x * w0.y + v.y * w1.y + v.z * w2.y + v.w * w3.y;
            a2 += v.x * w0.z + v.y * w1.z + v.z * w2.z + v.w * w3.z;
            a3 += v.x * w0.w + v.y * w1.w + v.z * w2.w + v.w * w3.w;
        }
#pragma unroll
        for (int o = 1; o < 4; o <<= 1) {
            a0 += __shfl_xor_sync(0xffffffffu, a0, o);
            a1 += __shfl_xor_sync(0xffffffffu, a1, o);
            a2 += __shfl_xor_sync(0xffffffffu, a2, o);
            a3 += __shfl_xor_sync(0xffffffffu, a3, o);
        }
        if (c == 0) s_attnT4[k] = make_float4(a0, a1, a2, a3);
    }
    __syncthreads();

    if (t < NH) s_qscore[t] = s_qp[0][t] + s_qp[1][t] + s_qp[2][t] + s_qp[3][t];
    __syncthreads();

    // softmax: warp h handles head h (lanes cover k and k+32)
    if (t < 128) {
        int h = t >> 5, l = t & 31;
        float qs = s_qscore[h];
        int m0 = mask[b * NN + l];
        int m1 = mask[b * NN + l + 32];
        float v0 = m0 ? -1e10f : qs + sc[l * 4 + h];
        float v1 = m1 ? -1e10f : qs + sc[(l + 32) * 4 + h];
        float mx = fmaxf(v0, v1);
#pragma unroll
        for (int o = 16; o > 0; o >>= 1) mx = fmaxf(mx, __shfl_xor_sync(0xffffffffu, mx, o));
        float e0 = expf(v0 - mx), e1 = expf(v1 - mx);
        float s = e0 + e1;
#pragma unroll
        for (int o = 16; o > 0; o >>= 1) s += __shfl_xor_sync(0xffffffffu, s, o);
        float inv = 1.f / s;
        e0 *= inv; e1 *= inv;
        sc[l * 4 + h] = e0;
        sc[(l + 32) * 4 + h] = e1;
        out_attn[b * (NH * NN) + h * NN + l]      = e0;
        out_attn[b * (NH * NN) + h * NN + l + 32] = e1;
    }
    __syncthreads();

    // pass 2: ctx[h][i] = sum_k attn[h][k] * k_in[k][i]; re-read k_in (L2-hot)
    {
        int i4 = t & 127, ks = t >> 7;
        int seg = i4 >> 5;
        int col4 = i4 & 31;
        const float* kin = (seg == 0) ? seq : (seg == 1) ? seqe : (seg == 2) ? seqt : seqp;
        const float4* base = (const float4*)(kin + (size_t)b * NN * DK) + col4;
        float4 c0 = make_float4(0.f, 0.f, 0.f, 0.f);
        float4 c1 = c0, c2 = c0, c3 = c0;
        int k0 = ks * 32;
#pragma unroll 4
        for (int k = k0; k < k0 + 32; k++) {
            float4 v = base[k * 32];
            float4 a = s_attnT4[k];
            c0.x += a.x * v.x; c0.y += a.x * v.y; c0.z += a.x * v.z; c0.w += a.x * v.w;
            c1.x += a.y * v.x; c1.y += a.y * v.y; c1.z += a.y * v.z; c1.w += a.y * v.w;
            c2.x += a.z * v.x; c2.y += a.z * v.y; c2.z += a.z * v.z; c2.w += a.z * v.w;
            c3.x += a.w * v.x; c3.y += a.w * v.y; c3.z += a.w * v.z; c3.w += a.w * v.w;
        }
        if (ks) {
            s_part[i4 * 4 + 0] = c0; s_part[i4 * 4 + 1] = c1;
            s_part[i4 * 4 + 2] = c2; s_part[i4 * 4 + 3] = c3;
        }
        __syncthreads();
        if (!ks) {
            float4 p0 = s_part[i4 * 4 + 0], p1 = s_part[i4 * 4 + 1];
            float4 p2 = s_part[i4 * 4 + 2], p3 = s_part[i4 * 4 + 3];
            c0.x += p0.x; c0.y += p0.y; c0.z += p0.z; c0.w += p0.w;
            c1.x += p1.x; c1.y += p1.y; c1.z += p1.z; c1.w += p1.w;
            c2.x += p2.x; c2.y += p2.y; c2.z += p2.z; c2.w += p2.w;
            c3.x += p3.x; c3.y += p3.y; c3.z += p3.z; c3.w += p3.w;
            float4* gc = (float4*)(g_ctx + (size_t)b * NH * DM);
            gc[0 * 128 + i4] = c0;
            gc[1 * 128 + i4] = c1;
            gc[2 * 128 + i4] = c2;
            gc[3 * 128 + i4] = c3;
        }
    }
}

// ---------------------------------------------------------------------------
// K2: tail — ctx@Wv -> leaky(fc) -> residual+LN -> relu(fc1) -> fc2 -> z
// grid 128 (TB=16 batches/CTA), block 256, dynamic smem
// ---------------------------------------------------------------------------
__global__ void __launch_bounds__(256) tail_kernel(
    const float* __restrict__ src,  const float* __restrict__ srct,
    const float* __restrict__ srcp,
    const float* __restrict__ Wv,   const float* __restrict__ fcw,
    const float* __restrict__ fcb,  const float* __restrict__ lng,
    const float* __restrict__ lnb,  const float* __restrict__ fc1w,
    const float* __restrict__ fc1b, const float* __restrict__ fc2w,
    const float* __restrict__ fc2b, float* __restrict__ zout)
{
    extern __shared__ float sm[];
    float* ctx_s = sm;                          // [TB][2048]
    float* out_s = sm + TB * 2048;              // [TB][512]
    float* src_s = sm + TB * 2048 + TB * 512;   // [TB][128]
    float* ln_s  = sm;                          // alias over ctx_s: [TB][512]
    float* h1_s  = sm + TB * 512;               // alias over ctx_s tail: [TB][128]

    int b0 = blockIdx.x * TB;
    int t = threadIdx.x;

    {
        const float4* gc = (const float4*)(g_ctx + (size_t)b0 * NH * DM);
        float4* c4 = (float4*)ctx_s;
        for (int idx = t; idx < TB * NH * DM / 4; idx += 256) c4[idx] = gc[idx];
        const float4* gs = (const float4*)(src + (size_t)b0 * DK);
        float4* s4 = (float4*)src_s;
        for (int idx = t; idx < TB * DK / 4; idx += 256) s4[idx] = gs[idx];
    }
    __syncthreads();

    int d = t & 127, tq = t >> 7;

    // GEMM A: out[t][h*128+d] = sum_i ctx[t][h][i] * Wv[i][h*128+d]
    for (int h = 0; h < NH; h++) {
        float acc[8];
#pragma unroll
        for (int r = 0; r < 8; r++) acc[r] = 0.f;
        const float* wcol = Wv + h * DK + d;
        for (int i = 0; i < DM; i += 4) {
            float w0 = wcol[(i + 0) * DM];
            float w1 = wcol[(i + 1) * DM];
            float w2 = wcol[(i + 2) * DM];
            float w3 = wcol[(i + 3) * DM];
#pragma unroll
            for (int r = 0; r < 8; r++) {
                float4 cv = *(const float4*)(ctx_s + (tq * 8 + r) * 2048 + h * DM + i);
                acc[r] += cv.x * w0 + cv.y * w1 + cv.z * w2 + cv.w * w3;
            }
        }
#pragma unroll
        for (int r = 0; r < 8; r++)
            out_s[(tq * 8 + r) * DM + h * DK + d] = acc[r];
    }
    __syncthreads();

    // GEMM B: fc + leaky_relu(0.2) -> ln_s (pre-LN values)
    for (int g = 0; g < 2; g++) {
        int col = g * 256 + t;
        float acc[TB];
#pragma unroll
        for (int r = 0; r < TB; r++) acc[r] = 0.f;
        const float* wcol = fcw + col;
        for (int i = 0; i < DM; i += 4) {
            float w0 = wcol[(i + 0) * DM];
            float w1 = wcol[(i + 1) * DM];
            float w2 = wcol[(i + 2) * DM];
            float w3 = wcol[(i + 3) * DM];
#pragma unroll
            for (int r = 0; r < TB; r++) {
                float4 xv = *(const float4*)(out_s + r * DM + i);
                acc[r] += xv.x * w0 + xv.y * w1 + xv.z * w2 + xv.w * w3;
            }
        }
        float bias = fcb[col];
#pragma unroll
        for (int r = 0; r < TB; r++) {
            float v = acc[r] + bias;
            v = (v > 0.f) ? v : 0.2f * v;
            ln_s[r * DM + col] = v;
        }
    }
    __syncthreads();

    // residual (+q_in) + layernorm, in place in ln_s
    {
        int w = t >> 5, l = t & 31;
#pragma unroll
        for (int rr = 0; rr < 2; rr++) {
            int row = w * 2 + rr;
            int gb = b0 + row;
            float y[16];
            float sum = 0.f, sumsq = 0.f;
#pragma unroll
            for (int e = 0; e < 16; e++) {
                int j = l + e * 32;
                float q;
                if (j < 128)       q = src_s[row * DK + j];
                else if (j < 256)  q = 0.f;
                else if (j < 384)  q = srct[gb * DK + (j - 256)];
                else               q = srcp[gb * DK + (j - 384)];
                float v = ln_s[row * DM + j] + q;
                y[e] = v; sum += v; sumsq += v * v;
            }
#pragma unroll
            for (int o = 16; o > 0; o >>= 1) {
                sum   += __shfl_xor_sync(0xffffffffu, sum, o);
                sumsq += __shfl_xor_sync(0xffffffffu, sumsq, o);
            }
            float mu  = sum * (1.f / 512.f);
            float var = sumsq * (1.f / 512.f) - mu * mu;
            float inv = rsqrtf(var + 1e-5f);
#pragma unroll
            for (int e = 0; e < 16; e++) {
                int j = l + e * 32;
                ln_s[row * DM + j] = (y[e] - mu) * inv * lng[j] + lnb[j];
            }
        }
    }
    __syncthreads();

    int m = t & 127;

    // Merge fc1: x = [ln(512) | src(128)] @ fc1_w + b, relu -> h1_s
    {
        float acc[8];
#pragma unroll
        for (int r = 0; r < 8; r++) acc[r] = 0.f;
        const float* w1col = fc1w + m;
        for (int j = 0; j < DM; j += 4) {
            float w0 = w1col[(j + 0) * DK];
            float w1 = w1col[(j + 1) * DK];
            float w2 = w1col[(j + 2) * DK];
            float w3 = w1col[(j + 3) * DK];
#pragma unroll
            for (int r = 0; r < 8; r++) {
                float4 xv = *(const float4*)(ln_s + (tq * 8 + r) * DM + j);
                acc[r] += xv.x * w0 + xv.y * w1 + xv.z * w2 + xv.w * w3;
            }
        }
        for (int j = 0; j < DK; j += 4) {
            float w0 = w1col[(DM + j + 0) * DK];
            float w1 = w1col[(DM + j + 1) * DK];
            float w2 = w1col[(DM + j + 2) * DK];
            float w3 = w1col[(DM + j + 3) * DK];
#pragma unroll
            for (int r = 0; r < 8; r++) {
                float4 xv = *(const float4*)(src_s + (tq * 8 + r) * DK + j);
                acc[r] += xv.x * w0 + xv.y * w1 + xv.z * w2 + xv.w * w3;
            }
        }
        float b1 = fc1b[m];
#pragma unroll
        for (int r = 0; r < 8; r++)
            h1_s[(tq * 8 + r) * DK + m] = fmaxf(acc[r] + b1, 0.f);
    }
    __syncthreads();

    // Merge fc2 -> z
    {
        float acc[8];
#pragma unroll
        for (int r = 0; r < 8; r++) acc[r] = 0.f;
        const float* w2col = fc2w + m;
        for (int j = 0; j < DK; j += 4) {
            float w0 = w2col[(j + 0) * DK];
            float w1 = w2col[(j + 1) * DK];
            float w2 = w2col[(j + 2) * DK];
            float w3 = w2col[(j + 3) * DK];
#pragma unroll
            for (int r = 0; r < 8; r++) {
                float4 hv = *(const float4*)(h1_s + (tq * 8 + r) * DK + j);
                acc[r] += hv.x * w0 + hv.y * w1 + hv.z * w2 + hv.w * w3;
            }
        }
        float b2 = fc2b[m];
#pragma unroll
        for (int r = 0; r < 8; r++)
            zout[(size_t)(b0 + tq * 8 + r) * DK + m] = acc[r] + b2;
    }
}

// ---------------------------------------------------------------------------
extern "C" void kernel_launch(void* const* d_in, const int* in_sizes, int n_in,
                              void* d_out, int out_size) {
    (void)in_sizes; (void)n_in; (void)out_size;
    const float* src   = (const float*)d_in[0];
    const float* src_t = (const float*)d_in[1];
    const float* src_p = (const float*)d_in[2];
    const float* seq   = (const float*)d_in[3];
    const float* seq_t = (const float*)d_in[4];
    const float* seq_e = (const float*)d_in[5];
    const float* seq_p = (const float*)d_in[6];
    const int*   mask  = (const int*)d_in[7];
    const float* Wq    = (const float*)d_in[8];
    const float* Wk    = (const float*)d_in[9];
    const float* Wv    = (const float*)d_in[10];
    const float* w_map = (const float*)d_in[11];
    const float* fc_w  = (const float*)d_in[12];
    const float* fc_b  = (const float*)d_in[13];
    const float* ln_g  = (const float*)d_in[14];
    const float* ln_b  = (const float*)d_in[15];
    const float* fc1_w = (const float*)d_in[16];
    const float* fc1_b = (const float*)d_in[17];
    const float* fc2_w = (const float*)d_in[18];
    const float* fc2_b = (const float*)d_in[19];

    float* out      = (float*)d_out;
    float* z_out    = out;                 // [2048,1,128]
    float* attn_out = out + NB * DK;       // [2048,4,1,64]

    fold_kernel<<<2, 256>>>(Wq, Wk, w_map);
    attn_kernel<<<NB, 256>>>(src, src_t, src_p, seq, seq_e, seq_t, seq_p,
                             mask, attn_out);

    const int smem2 = (TB * 2048 + TB * 512 + TB * 128) * (int)sizeof(float);
    cudaFuncSetAttribute(tail_kernel, cudaFuncAttributeMaxDynamicSharedMemorySize, smem2);
    tail_kernel<<<NB / TB, 256, smem2>>>(src, src_t, src_p, Wv, fc_w, fc_b,
                                         ln_g, ln_b, fc1_w, fc1_b, fc2_w, fc2_b,
                                         z_out);
}

// round 2
// speedup vs baseline: 1.9905x; 1.9905x over previous
#include <cuda_runtime.h>

#define NB 2048
#define NN 64
#define DM 512
#define NH 4
#define DK 128
#define TB 16

__device__ float g_Wqf[DM * NH];
__device__ float g_Wkf[DM * NH];
__device__ float g_attnT[NB * NN * NH];   // [b][k][h] layout for K2

// ---------------------------------------------------------------------------
// K0: fold Wq/Wk with w_map halves. grid 512 (one i per CTA), block 128
// (warp = head). ~4us.
// ---------------------------------------------------------------------------
__global__ void __launch_bounds__(128) fold_kernel(
    const float* __restrict__ Wq, const float* __restrict__ Wk,
    const float* __restrict__ w_map)
{
    __shared__ float4 s_m[64];
    int i = blockIdx.x;
    int t = threadIdx.x;
    int lane = t & 31, h = t >> 5;
    if (t < 64) s_m[t] = ((const float4*)w_map)[t];
    __syncthreads();
    float4 vq = ((const float4*)(Wq + i * DM + h * DK))[lane];
    float4 vk = ((const float4*)(Wk + i * DM + h * DK))[lane];
    float4 mq = s_m[lane], mk = s_m[32 + lane];
    float sq = vq.x * mq.x + vq.y * mq.y + vq.z * mq.z + vq.w * mq.w;
    float sk = vk.x * mk.x + vk.y * mk.y + vk.z * mk.z + vk.w * mk.w;
#pragma unroll
    for (int o = 16; o > 0; o >>= 1) {
        sq += __shfl_xor_sync(0xffffffffu, sq, o);
        sk += __shfl_xor_sync(0xffffffffu, sk, o);
    }
    if (lane == 0) {
        g_Wqf[i * NH + h] = sq;
        g_Wkf[i * NH + h] = sk;
    }
}

// ---------------------------------------------------------------------------
// K1: scores + masked softmax only. grid 2048, block 256.
// Warp-per-row loads: every warp LDG covers one contiguous 128B chunk.
// ---------------------------------------------------------------------------
__global__ void __launch_bounds__(256) score_kernel(
    const float* __restrict__ src,  const float* __restrict__ srct,
    const float* __restrict__ srcp,
    const float* __restrict__ seq,  const float* __restrict__ seqe,
    const float* __restrict__ seqt, const float* __restrict__ seqp,
    const int*   __restrict__ mask, float* __restrict__ out_attn)
{
    __shared__ float4 s_wkf[DM];
    __shared__ float s_score[NH][NN];
    __shared__ float s_qp[4][NH];
    __shared__ float s_qs[NH];

    int b = blockIdx.x;
    int t = threadIdx.x;

    const float4* gwkf = (const float4*)g_Wkf;
    s_wkf[t]       = gwkf[t];
    s_wkf[t + 256] = gwkf[t + 256];

    // q_score partials (q_in nonzero segs: src, src_t, src_p)
    if (t < DK) {
        float a  = src[b * DK + t];
        float tt = srct[b * DK + t];
        float pp = srcp[b * DK + t];
        const float4* gwqf = (const float4*)g_Wqf;
        float4 w0 = gwqf[t];
        float4 w1 = gwqf[2 * DK + t];
        float4 w2 = gwqf[3 * DK + t];
        float q0 = a * w0.x + tt * w1.x + pp * w2.x;
        float q1 = a * w0.y + tt * w1.y + pp * w2.y;
        float q2 = a * w0.z + tt * w1.z + pp * w2.z;
        float q3 = a * w0.w + tt * w1.w + pp * w2.w;
#pragma unroll
        for (int o = 16; o > 0; o >>= 1) {
            q0 += __shfl_xor_sync(0xffffffffu, q0, o);
            q1 += __shfl_xor_sync(0xffffffffu, q1, o);
            q2 += __shfl_xor_sync(0xffffffffu, q2, o);
            q3 += __shfl_xor_sync(0xffffffffu, q3, o);
        }
        if ((t & 31) == 0) {
            int w = t >> 5;
            s_qp[w][0] = q0; s_qp[w][1] = q1; s_qp[w][2] = q2; s_qp[w][3] = q3;
        }
    }
    __syncthreads();

    // k_score: warp w handles rows k = w*8 .. w*8+7
    {
        int w = t >> 5, lane = t & 31;
#pragma unroll
        for (int r = 0; r < 8; r++) {
            int k = w * 8 + r;
            float a0 = 0.f, a1 = 0.f, a2 = 0.f, a3 = 0.f;
#pragma unroll
            for (int seg = 0; seg < 4; seg++) {
                const float* kin = (seg == 0) ? seq : (seg == 1) ? seqe
                                  : (seg == 2) ? seqt : seqp;
                const float* row = kin + (size_t)(b * NN + k) * DK;
#pragma unroll
                for (int j = 0; j < 4; j++) {
                    float v = row[j * 32 + lane];           // 128B coalesced
                    float4 wv = s_wkf[seg * DK + j * 32 + lane];
                    a0 += v * wv.x; a1 += v * wv.y;
                    a2 += v * wv.z; a3 += v * wv.w;
                }
            }
#pragma unroll
            for (int o = 16; o > 0; o >>= 1) {
                a0 += __shfl_xor_sync(0xffffffffu, a0, o);
                a1 += __shfl_xor_sync(0xffffffffu, a1, o);
                a2 += __shfl_xor_sync(0xffffffffu, a2, o);
                a3 += __shfl_xor_sync(0xffffffffu, a3, o);
            }
            if (lane == 0) {
                s_score[0][k] = a0; s_score[1][k] = a1;
                s_score[2][k] = a2; s_score[3][k] = a3;
            }
        }
    }
    __syncthreads();

    if (t < NH) s_qs[t] = s_qp[0][t] + s_qp[1][t] + s_qp[2][t] + s_qp[3][t];
    __syncthreads();

    // softmax: warp h handles head h
    if (t < 128) {
        int h = t >> 5, l = t & 31;
        float qs = s_qs[h];
        int m0 = mask[b * NN + l];
        int m1 = mask[b * NN + l + 32];
        float v0 = m0 ? -1e10f : qs + s_score[h][l];
        float v1 = m1 ? -1e10f : qs + s_score[h][l + 32];
        float mx = fmaxf(v0, v1);
#pragma unroll
        for (int o = 16; o > 0; o >>= 1) mx = fmaxf(mx, __shfl_xor_sync(0xffffffffu, mx, o));
        float e0 = expf(v0 - mx), e1 = expf(v1 - mx);
        float s = e0 + e1;
#pragma unroll
        for (int o = 16; o > 0; o >>= 1) s += __shfl_xor_sync(0xffffffffu, s, o);
        float inv = 1.f / s;
        e0 *= inv; e1 *= inv;
        out_attn[b * (NH * NN) + h * NN + l]      = e0;
        out_attn[b * (NH * NN) + h * NN + l + 32] = e1;
        g_attnT[(size_t)(b * NN + l) * NH + h]      = e0;
        g_attnT[(size_t)(b * NN + l + 32) * NH + h] = e1;
    }
}

// ---------------------------------------------------------------------------
// K2: fused ctx (= attn @ k_in, streamed from DRAM) -> ctx@Wv -> leaky(fc)
//     -> residual+LN -> relu(fc1) -> fc2 -> z.
// grid 128 (TB=16 batches/CTA), block 256, 184KB dyn smem.
// All GEMMs: thread owns output column(s); activations via broadcast LDS.128
// -> FMA-bound instead of LDS-bound.
// ---------------------------------------------------------------------------
// smem float offsets
#define SM_CTX  0        // [TB][2048]  (32768) ; aliases: LN [TB][512], H1, PART
#define SM_ATT  32768    // [TB][64] float4 (4096)
#define SM_OUT  36864    // [TB][512]   (8192)
#define SM_SRC  45056    // [TB][128]   (2048)
#define SM_TOTF 47104
#define SM_H1   8192
#define SM_PART 10240    // [128][17]

__global__ void __launch_bounds__(256) tail_kernel(
    const float* __restrict__ src,  const float* __restrict__ srct,
    const float* __restrict__ srcp,
    const float* __restrict__ seq,  const float* __restrict__ seqe,
    const float* __restrict__ seqt, const float* __restrict__ seqp,
    const float* __restrict__ Wv,   const float* __restrict__ fcw,
    const float* __restrict__ fcb,  const float* __restrict__ lng,
    const float* __restrict__ lnb,  const float* __restrict__ fc1w,
    const float* __restrict__ fc1b, const float* __restrict__ fc2w,
    const float* __restrict__ fc2b, float* __restrict__ zout)
{
    extern __shared__ float sm[];
    float4* ctx4 = (float4*)sm;
    float4* att4 = (float4*)(sm + SM_ATT);
    float*  out_s = sm + SM_OUT;
    float4* out4  = (float4*)out_s;
    float*  src_s = sm + SM_SRC;
    float4* src4  = (float4*)src_s;
    float*  ln_s  = sm;                    // alias over ctx
    float4* ln4   = (float4*)sm;
    float*  h1_s  = sm + SM_H1;
    float4* h14   = (float4*)h1_s;
    float*  part  = sm + SM_PART;

    int t = threadIdx.x;
    int b0 = blockIdx.x * TB;

    // stage attn (transposed) + src
    {
        const float4* ga = (const float4*)(g_attnT + (size_t)b0 * NN * NH);
        for (int idx = t; idx < TB * NN; idx += 256) att4[idx] = ga[idx];
        const float4* gs = (const float4*)(src + (size_t)b0 * DK);
        for (int idx = t; idx < TB * DK / 4; idx += 256) src4[idx] = gs[idx];
    }
    __syncthreads();

    int rb = t >> 7, c4 = t & 127;

    // Phase 1: ctx[r][h][i] = sum_k attn[r][k][h] * k_in[r][k][i]  (DRAM stream)
    {
        int seg = c4 >> 5, col = c4 & 31;
        const float* kin = (seg == 0) ? seq : (seg == 1) ? seqe
                          : (seg == 2) ? seqt : seqp;
#pragma unroll 1
        for (int rp = 0; rp < TB / 2; rp++) {
            int r = rp * 2 + rb;
            const float4* base = (const float4*)(kin + (size_t)(b0 + r) * NN * DK) + col;
            float4 A0 = make_float4(0.f, 0.f, 0.f, 0.f);
            float4 A1 = A0, A2 = A0, A3 = A0;
#pragma unroll 4
            for (int k = 0; k < NN; k++) {
                float4 v = base[k * 32];
                float4 a = att4[r * NN + k];
                A0.x += a.x * v.x; A0.y += a.x * v.y; A0.z += a.x * v.z; A0.w += a.x * v.w;
                A1.x += a.y * v.x; A1.y += a.y * v.y; A1.z += a.y * v.z; A1.w += a.y * v.w;
                A2.x += a.z * v.x; A2.y += a.z * v.y; A2.z += a.z * v.z; A2.w += a.z * v.w;
                A3.x += a.w * v.x; A3.y += a.w * v.y; A3.z += a.w * v.z; A3.w += a.w * v.w;
            }
            ctx4[r * 512 + 0 * 128 + c4] = A0;
            ctx4[r * 512 + 1 * 128 + c4] = A1;
            ctx4[r * 512 + 2 * 128 + c4] = A2;
            ctx4[r * 512 + 3 * 128 + c4] = A3;
        }
    }
    __syncthreads();

    int d = c4;

    // Phase 2: GEMM A  out[r][h*128+d] = sum_i ctx[r][h][i]*Wv[i][h*128+d]
#pragma unroll 1
    for (int hh = 0; hh < 2; hh++) {
        int h = rb + hh * 2;
        float acc[TB];
#pragma unroll
        for (int r = 0; r < TB; r++) acc[r] = 0.f;
        const float* wcol = Wv + h * DK + d;
#pragma unroll 2
        for (int i4 = 0; i4 < 128; i4++) {
            int i = i4 * 4;
            float w0 = wcol[(i + 0) * DM];
            float w1 = wcol[(i + 1) * DM];
            float w2 = wcol[(i + 2) * DM];
            float w3 = wcol[(i + 3) * DM];
#pragma unroll
            for (int r = 0; r < TB; r++) {
                float4 c = ctx4[r * 512 + h * 128 + i4];   // broadcast
                acc[r] += c.x * w0 + c.y * w1 + c.z * w2 + c.w * w3;
            }
        }
#pragma unroll
        for (int r = 0; r < TB; r++) out_s[r * DM + h * DK + d] = acc[r];
    }
    __syncthreads();

    // Phase 3: GEMM B  fc + leaky -> ln_s ; thread owns cols t and t+256
    {
        float accB0[TB], accB1[TB];
#pragma unroll
        for (int r = 0; r < TB; r++) { accB0[r] = 0.f; accB1[r] = 0.f; }
        const float* w0col = fcw + t;
        const float* w1col = fcw + t + 256;
#pragma unroll 2
        for (int i4 = 0; i4 < 128; i4++) {
            int i = i4 * 4;
            float p0 = w0col[(i + 0) * DM], p1 = w0col[(i + 1) * DM];
            float p2 = w0col[(i + 2) * DM], p3 = w0col[(i + 3) * DM];
            float q0 = w1col[(i + 0) * DM], q1 = w1col[(i + 1) * DM];
            float q2 = w1col[(i + 2) * DM], q3 = w1col[(i + 3) * DM];
#pragma unroll
            for (int r = 0; r < TB; r++) {
                float4 x = out4[r * 128 + i4];             // broadcast
                accB0[r] += x.x * p0 + x.y * p1 + x.z * p2 + x.w * p3;
                accB1[r] += x.x * q0 + x.y * q1 + x.z * q2 + x.w * q3;
            }
        }
        float bb0 = fcb[t], bb1 = fcb[t + 256];
#pragma unroll
        for (int r = 0; r < TB; r++) {
            float v0 = accB0[r] + bb0; v0 = (v0 > 0.f) ? v0 : 0.2f * v0;
            float v1 = accB1[r] + bb1; v1 = (v1 > 0.f) ? v1 : 0.2f * v1;
            ln_s[r * DM + t]       = v0;
            ln_s[r * DM + t + 256] = v1;
        }
    }
    __syncthreads();

    // Phase 4: residual (+q_in) + layernorm, in place in ln_s
    {
        int w = t >> 5, l = t & 31;
#pragma unroll
        for (int rr = 0; rr < 2; rr++) {
            int row = w * 2 + rr;
            int gb = b0 + row;
            float y[16];
            float sum = 0.f, sumsq = 0.f;
#pragma unroll
            for (int e = 0; e < 16; e++) {
                int j = l + e * 32;
                float q;
                if (j < 128)       q = src_s[row * DK + j];
                else if (j < 256)  q = 0.f;
                else if (j < 384)  q = srct[gb * DK + (j - 256)];
                else               q = srcp[gb * DK + (j - 384)];
                float v = ln_s[row * DM + j] + q;
                y[e] = v; sum += v; sumsq += v * v;
            }
#pragma unroll
            for (int o = 16; o > 0; o >>= 1) {
                sum   += __shfl_xor_sync(0xffffffffu, sum, o);
                sumsq += __shfl_xor_sync(0xffffffffu, sumsq, o);
            }
            float mu  = sum * (1.f / 512.f);
            float var = sumsq * (1.f / 512.f) - mu * mu;
            float inv = rsqrtf(var + 1e-5f);
#pragma unroll
            for (int e = 0; e < 16; e++) {
                int j = l + e * 32;
                ln_s[row * DM + j] = (y[e] - mu) * inv * lng[j] + lnb[j];
            }
        }
    }
    __syncthreads();

    int kh = rb;

    // Phase 5: fc1 (K=640 split 2 ways) + relu -> h1_s
    {
        float a1[TB];
#pragma unroll
        for (int r = 0; r < TB; r++) a1[r] = 0.f;
        const float* wcol = fc1w + d;
        int i40 = kh * 64;
#pragma unroll 2
        for (int i4 = i40; i4 < i40 + 64; i4++) {
            int j = i4 * 4;
            float w0 = wcol[(j + 0) * DK], w1 = wcol[(j + 1) * DK];
            float w2 = wcol[(j + 2) * DK], w3 = wcol[(j + 3) * DK];
#pragma unroll
            for (int r = 0; r < TB; r++) {
                float4 x = ln4[r * 128 + i4];              // broadcast
                a1[r] += x.x * w0 + x.y * w1 + x.z * w2 + x.w * w3;
            }
        }
        int j40 = kh * 16;
#pragma unroll 2
        for (int j4 = j40; j4 < j40 + 16; j4++) {
            int j = j4 * 4;
            float w0 = wcol[(DM + j + 0) * DK], w1 = wcol[(DM + j + 1) * DK];
            float w2 = wcol[(DM + j + 2) * DK], w3 = wcol[(DM + j + 3) * DK];
#pragma unroll
            for (int r = 0; r < TB; r++) {
                float4 x = src4[r * 32 + j4];              // broadcast
                a1[r] += x.x * w0 + x.y * w1 + x.z * w2 + x.w * w3;
            }
        }
        if (kh == 1) {
#pragma unroll
            for (int r = 0; r < TB; r++) part[d * 17 + r] = a1[r];
        }
        __syncthreads();
        if (kh == 0) {
            float bb = fc1b[d];
#pragma unroll
            for (int r = 0; r < TB; r++)
                h1_s[r * DK + d] = fmaxf(a1[r] + part[d * 17 + r] + bb, 0.f);
        }
        __syncthreads();
    }

    // Phase 6: fc2 (K=128 split 2 ways) -> z
    {
        float a2[TB];
#pragma unroll
        for (int r = 0; r < TB; r++) a2[r] = 0.f;
        const float* wcol = fc2w + d;
        int j40 = kh * 16;
#pragma unroll 2
        for (int j4 = j40; j4 < j40 + 16; j4++) {
            int j = j4 * 4;
            float w0 = wcol[(j + 0) * DK], w1 = wcol[(j + 1) * DK];
            float w2 = wcol[(j + 2) * DK], w3 = wcol[(j + 3) * DK];
#pragma unroll
            for (int r = 0; r < TB; r++) {
                float4 x = h14[r * 32 + j4];               // broadcast
                a2[r] += x.x * w0 + x.y * w1 + x.z * w2 + x.w * w3;
            }
        }
        if (kh == 1) {
#pragma unroll
            for (int r = 0; r < TB; r++) part[d * 17 + r] = a2[r];
        }
        __syncthreads();
        if (kh == 0) {
            float bb = fc2b[d];
#pragma unroll
            for (int r = 0; r < TB; r++)
                zout[(size_t)(b0 + r) * DK + d] = a2[r] + part[d * 17 + r] + bb;
        }
    }
}

// ---------------------------------------------------------------------------
extern "C" void kernel_launch(void* const* d_in, const int* in_sizes, int n_in,
                              void* d_out, int out_size) {
    (void)in_sizes; (void)n_in; (void)out_size;
    const float* src   = (const float*)d_in[0];
    const float* src_t = (const float*)d_in[1];
    const float* src_p = (const float*)d_in[2];
    const float* seq   = (const float*)d_in[3];
    const float* seq_t = (const float*)d_in[4];
    const float* seq_e = (const float*)d_in[5];
    const float* seq_p = (const float*)d_in[6];
    const int*   mask  = (const int*)d_in[7];
    const float* Wq    = (const float*)d_in[8];
    const float* Wk    = (const float*)d_in[9];
    const float* Wv    = (const float*)d_in[10];
    const float* w_map = (const float*)d_in[11];
    const float* fc_w  = (const float*)d_in[12];
    const float* fc_b  = (const float*)d_in[13];
    const float* ln_g  = (const float*)d_in[14];
    const float* ln_b  = (const float*)d_in[15];
    const float* fc1_w = (const float*)d_in[16];
    const float* fc1_b = (const float*)d_in[17];
    const float* fc2_w = (const float*)d_in[18];
    const float* fc2_b = (const float*)d_in[19];

    float* out      = (float*)d_out;
    float* z_out    = out;                 // [2048,1,128]
    float* attn_out = out + NB * DK;       // [2048,4,1,64]

    fold_kernel<<<DM, 128>>>(Wq, Wk, w_map);
    score_kernel<<<NB, 256>>>(src, src_t, src_p, seq, seq_e, seq_t, seq_p,
                              mask, attn_out);

    const int smem2 = SM_TOTF * (int)sizeof(float);
    cudaFuncSetAttribute(tail_kernel, cudaFuncAttributeMaxDynamicSharedMemorySize, smem2);
    tail_kernel<<<NB / TB, 256, smem2>>>(src, src_t, src_p,
                                         seq, seq_e, seq_t, seq_p,
                                         Wv, fc_w, fc_b, ln_g, ln_b,
                                         fc1_w, fc1_b, fc2_w, fc2_b, z_out);
}

// round 3
// speedup vs baseline: 2.8498x; 1.4317x over previous
#include <cuda_runtime.h>

#define NB 2048
#define NN 64
#define DM 512
#define NH 4
#define DK 128
#define TB 8

typedef unsigned long long ull;

__device__ float g_Wqf[DM * NH];
__device__ float g_Wkf[DM * NH];
__device__ float g_attnT[NB * NN * NH];   // [b][k][h]

// ---- f32x2 packed-FMA helpers (sm_100+) ------------------------------------
__device__ __forceinline__ ull pk(float a, float b) {
    ull r; asm("mov.b64 %0,{%1,%2};" : "=l"(r) : "f"(a), "f"(b)); return r;
}
__device__ __forceinline__ void fma2(ull &d, ull a, ull b) {
    asm("fma.rn.f32x2 %0,%1,%2,%0;" : "+l"(d) : "l"(a), "l"(b));
}
__device__ __forceinline__ float2 up(ull a) {
    float2 f; asm("mov.b64 {%0,%1},%2;" : "=f"(f.x), "=f"(f.y) : "l"(a)); return f;
}

// ---------------------------------------------------------------------------
// K0: fold Wq/Wk with w_map halves. grid 512, block 128 (warp = head).
// ---------------------------------------------------------------------------
__global__ void __launch_bounds__(128) fold_kernel(
    const float* __restrict__ Wq, const float* __restrict__ Wk,
    const float* __restrict__ w_map)
{
    __shared__ float4 s_m[64];
    int i = blockIdx.x;
    int t = threadIdx.x;
    int lane = t & 31, h = t >> 5;
    if (t < 64) s_m[t] = ((const float4*)w_map)[t];
    __syncthreads();
    float4 vq = ((const float4*)(Wq + i * DM + h * DK))[lane];
    float4 vk = ((const float4*)(Wk + i * DM + h * DK))[lane];
    float4 mq = s_m[lane], mk = s_m[32 + lane];
    float sq = vq.x * mq.x + vq.y * mq.y + vq.z * mq.z + vq.w * mq.w;
    float sk = vk.x * mk.x + vk.y * mk.y + vk.z * mk.z + vk.w * mk.w;
#pragma unroll
    for (int o = 16; o > 0; o >>= 1) {
        sq += __shfl_xor_sync(0xffffffffu, sq, o);
        sk += __shfl_xor_sync(0xffffffffu, sk, o);
    }
    if (lane == 0) {
        g_Wqf[i * NH + h] = sq;
        g_Wkf[i * NH + h] = sk;
    }
}

// ---------------------------------------------------------------------------
// K1: scores + masked softmax. grid 2048, block 256. (unchanged from R2)
// ---------------------------------------------------------------------------
__global__ void __launch_bounds__(256) score_kernel(
    const float* __restrict__ src,  const float* __restrict__ srct,
    const float* __restrict__ srcp,
    const float* __restrict__ seq,  const float* __restrict__ seqe,
    const float* __restrict__ seqt, const float* __restrict__ seqp,
    const int*   __restrict__ mask, float* __restrict__ out_attn)
{
    __shared__ float4 s_wkf[DM];
    __shared__ float s_score[NH][NN];
    __shared__ float s_qp[4][NH];
    __shared__ float s_qs[NH];

    int b = blockIdx.x;
    int t = threadIdx.x;

    const float4* gwkf = (const float4*)g_Wkf;
    s_wkf[t]       = gwkf[t];
    s_wkf[t + 256] = gwkf[t + 256];

    if (t < DK) {
        float a  = src[b * DK + t];
        float tt = srct[b * DK + t];
        float pp = srcp[b * DK + t];
        const float4* gwqf = (const float4*)g_Wqf;
        float4 w0 = gwqf[t];
        float4 w1 = gwqf[2 * DK + t];
        float4 w2 = gwqf[3 * DK + t];
        float q0 = a * w0.x + tt * w1.x + pp * w2.x;
        float q1 = a * w0.y + tt * w1.y + pp * w2.y;
        float q2 = a * w0.z + tt * w1.z + pp * w2.z;
        float q3 = a * w0.w + tt * w1.w + pp * w2.w;
#pragma unroll
        for (int o = 16; o > 0; o >>= 1) {
            q0 += __shfl_xor_sync(0xffffffffu, q0, o);
            q1 += __shfl_xor_sync(0xffffffffu, q1, o);
            q2 += __shfl_xor_sync(0xffffffffu, q2, o);
            q3 += __shfl_xor_sync(0xffffffffu, q3, o);
        }
        if ((t & 31) == 0) {
            int w = t >> 5;
            s_qp[w][0] = q0; s_qp[w][1] = q1; s_qp[w][2] = q2; s_qp[w][3] = q3;
        }
    }
    __syncthreads();

    {
        int w = t >> 5, lane = t & 31;
#pragma unroll
        for (int r = 0; r < 8; r++) {
            int k = w * 8 + r;
            float a0 = 0.f, a1 = 0.f, a2 = 0.f, a3 = 0.f;
#pragma unroll
            for (int seg = 0; seg < 4; seg++) {
                const float* kin = (seg == 0) ? seq : (seg == 1) ? seqe
                                  : (seg == 2) ? seqt : seqp;
                const float* row = kin + (size_t)(b * NN + k) * DK;
#pragma unroll
                for (int j = 0; j < 4; j++) {
                    float v = row[j * 32 + lane];
                    float4 wv = s_wkf[seg * DK + j * 32 + lane];
                    a0 += v * wv.x; a1 += v * wv.y;
                    a2 += v * wv.z; a3 += v * wv.w;
                }
            }
#pragma unroll
            for (int o = 16; o > 0; o >>= 1) {
                a0 += __shfl_xor_sync(0xffffffffu, a0, o);
                a1 += __shfl_xor_sync(0xffffffffu, a1, o);
                a2 += __shfl_xor_sync(0xffffffffu, a2, o);
                a3 += __shfl_xor_sync(0xffffffffu, a3, o);
            }
            if (lane == 0) {
                s_score[0][k] = a0; s_score[1][k] = a1;
                s_score[2][k] = a2; s_score[3][k] = a3;
            }
        }
    }
    __syncthreads();

    if (t < NH) s_qs[t] = s_qp[0][t] + s_qp[1][t] + s_qp[2][t] + s_qp[3][t];
    __syncthreads();

    if (t < 128) {
        int h = t >> 5, l = t & 31;
        float qs = s_qs[h];
        int m0 = mask[b * NN + l];
        int m1 = mask[b * NN + l + 32];
        float v0 = m0 ? -1e10f : qs + s_score[h][l];
        float v1 = m1 ? -1e10f : qs + s_score[h][l + 32];
        float mx = fmaxf(v0, v1);
#pragma unroll
        for (int o = 16; o > 0; o >>= 1) mx = fmaxf(mx, __shfl_xor_sync(0xffffffffu, mx, o));
        float e0 = expf(v0 - mx), e1 = expf(v1 - mx);
        float s = e0 + e1;
#pragma unroll
        for (int o = 16; o > 0; o >>= 1) s += __shfl_xor_sync(0xffffffffu, s, o);
        float inv = 1.f / s;
        e0 *= inv; e1 *= inv;
        out_attn[b * (NH * NN) + h * NN + l]      = e0;
        out_attn[b * (NH * NN) + h * NN + l + 32] = e1;
        g_attnT[(size_t)(b * NN + l) * NH + h]      = e0;
        g_attnT[(size_t)(b * NN + l + 32) * NH + h] = e1;
    }
}

// ---------------------------------------------------------------------------
// K2: fused ctx + GEMM chain, TB=8 batches/CTA, 256 CTAs, 2 CTAs/SM.
// All GEMM inner loops use packed fma.rn.f32x2 (FFMA2).
// ---------------------------------------------------------------------------
// smem float offsets
#define SM_CTX  0                 // [8][2048] (16384 f) ; alias ln[8][512], h1, part
#define SM_ATT  16384             // [8][64] float4 (2048 f)
#define SM_OUT  18432             // [8][512]  (4096 f)
#define SM_SRC  22528             // [8][128]  (1024 f)
#define SM_TOTF 23552
#define SM_H1   4096              // alias in ctx region
#define SM_PART 5120              // [128][9]

__global__ void __launch_bounds__(256, 2) tail_kernel(
    const float* __restrict__ src,  const float* __restrict__ srct,
    const float* __restrict__ srcp,
    const float* __restrict__ seq,  const float* __restrict__ seqe,
    const float* __restrict__ seqt, const float* __restrict__ seqp,
    const float* __restrict__ Wv,   const float* __restrict__ fcw,
    const float* __restrict__ fcb,  const float* __restrict__ lng,
    const float* __restrict__ lnb,  const float* __restrict__ fc1w,
    const float* __restrict__ fc1b, const float* __restrict__ fc2w,
    const float* __restrict__ fc2b, float* __restrict__ zout)
{
    extern __shared__ float sm[];
    ulonglong2* ctxU = (ulonglong2*)sm;
    float4*     att4 = (float4*)(sm + SM_ATT);
    float*      out_s = sm + SM_OUT;
    ulonglong2* outU  = (ulonglong2*)out_s;
    float*      src_s = sm + SM_SRC;
    ulonglong2* srcU  = (ulonglong2*)src_s;
    float*      ln_s  = sm;
    ulonglong2* lnU   = (ulonglong2*)sm;
    float*      h1_s  = sm + SM_H1;
    ulonglong2* h1U   = (ulonglong2*)h1_s;
    float*      part  = sm + SM_PART;

    int t = threadIdx.x;
    int b0 = blockIdx.x * TB;

    // stage attn (transposed) + src
    {
        const float4* ga = (const float4*)(g_attnT + (size_t)b0 * NN * NH);
        for (int idx = t; idx < TB * NN; idx += 256) att4[idx] = ga[idx];
        const float4* gs = (const float4*)(src + (size_t)b0 * DK);
        float4* s4 = (float4*)src_s;
        for (int idx = t; idx < TB * DK / 4; idx += 256) s4[idx] = gs[idx];
    }
    __syncthreads();

    int hb = t >> 7;          // 0/1
    int c4 = t & 127;

    // Phase 1: ctx[r][h][i] = sum_k attn[r][k][h] * k_in[r][k][i]
    // 2 independent row streams + 1-deep prefetch for MLP.
    {
        int seg = c4 >> 5, col = c4 & 31;
        const float* kin = (seg == 0) ? seq : (seg == 1) ? seqe
                          : (seg == 2) ? seqt : seqp;
#pragma unroll 1
        for (int rp = 0; rp < 2; rp++) {
            int r0 = hb * 4 + rp * 2;
            int r1 = r0 + 1;
            const ulonglong2* p0 = (const ulonglong2*)(kin + (size_t)(b0 + r0) * NN * DK) + col;
            const ulonglong2* p1 = (const ulonglong2*)(kin + (size_t)(b0 + r1) * NN * DK) + col;
            ull Ax[NH], Ay[NH], Bx[NH], By[NH];
#pragma unroll
            for (int h = 0; h < NH; h++) { Ax[h] = 0; Ay[h] = 0; Bx[h] = 0; By[h] = 0; }
            ulonglong2 va = p0[0], vb = p1[0];
#pragma unroll 4
            for (int k = 0; k < NN; k++) {
                ulonglong2 van, vbn;
                if (k < NN - 1) { van = p0[(k + 1) * 32]; vbn = p1[(k + 1) * 32]; }
                float4 a0 = att4[r0 * NN + k];
                float4 a1 = att4[r1 * NN + k];
                ull e00 = pk(a0.x, a0.x), e01 = pk(a0.y, a0.y);
                ull e02 = pk(a0.z, a0.z), e03 = pk(a0.w, a0.w);
                ull e10 = pk(a1.x, a1.x), e11 = pk(a1.y, a1.y);
                ull e12 = pk(a1.z, a1.z), e13 = pk(a1.w, a1.w);
                fma2(Ax[0], e00, va.x); fma2(Ay[0], e00, va.y);
                fma2(Ax[1], e01, va.x); fma2(Ay[1], e01, va.y);
                fma2(Ax[2], e02, va.x); fma2(Ay[2], e02, va.y);
                fma2(Ax[3], e03, va.x); fma2(Ay[3], e03, va.y);
                fma2(Bx[0], e10, vb.x); fma2(By[0], e10, vb.y);
                fma2(Bx[1], e11, vb.x); fma2(By[1], e11, vb.y);
                fma2(Bx[2], e12, vb.x); fma2(By[2], e12, vb.y);
                fma2(Bx[3], e13, vb.x); fma2(By[3], e13, vb.y);
                va = van; vb = vbn;
            }
#pragma unroll
            for (int h = 0; h < NH; h++) {
                ulonglong2 u; u.x = Ax[h]; u.y = Ay[h];
                ctxU[r0 * 512 + h * 128 + c4] = u;
                ulonglong2 w; w.x = Bx[h]; w.y = By[h];
                ctxU[r1 * 512 + h * 128 + c4] = w;
            }
        }
    }
    __syncthreads();

    int d = c4;

    // Phase 2: GEMM A  out[r][h*128+d] = sum_i ctx[r][h][i]*Wv[i][h*128+d]
#pragma unroll 1
    for (int hh = 0; hh < 2; hh++) {
        int h = hh * 2 + hb;
        ull acc[TB];
#pragma unroll
        for (int r = 0; r < TB; r++) acc[r] = 0;
        const float* wcol = Wv + h * DK + d;
#pragma unroll 2
        for (int i4 = 0; i4 < 128; i4++) {
            int i = i4 * 4;
            float w0 = wcol[(i + 0) * DM];
            float w1 = wcol[(i + 1) * DM];
            float w2 = wcol[(i + 2) * DM];
            float w3 = wcol[(i + 3) * DM];
            ull wA = pk(w0, w1), wB = pk(w2, w3);
#pragma unroll
            for (int r = 0; r < TB; r++) {
                ulonglong2 c = ctxU[r * 512 + h * 128 + i4];   // broadcast
                fma2(acc[r], c.x, wA);
                fma2(acc[r], c.y, wB);
            }
        }
#pragma unroll
        for (int r = 0; r < TB; r++) {
            float2 f = up(acc[r]);
            out_s[r * DM + h * DK + d] = f.x + f.y;
        }
    }
    __syncthreads();

    // Phase 3: GEMM B  fc + leaky -> ln_s ; thread owns cols t and t+256
    {
        ull acc0[TB], acc1[TB];
#pragma unroll
        for (int r = 0; r < TB; r++) { acc0[r] = 0; acc1[r] = 0; }
        const float* w0col = fcw + t;
        const float* w1col = fcw + t + 256;
#pragma unroll 2
        for (int i4 = 0; i4 < 128; i4++) {
            int i = i4 * 4;
            float p0 = w0col[(i + 0) * DM], p1 = w0col[(i + 1) * DM];
            float p2 = w0col[(i + 2) * DM], p3 = w0col[(i + 3) * DM];
            float q0 = w1col[(i + 0) * DM], q1 = w1col[(i + 1) * DM];
            float q2 = w1col[(i + 2) * DM], q3 = w1col[(i + 3) * DM];
            ull pA = pk(p0, p1), pB = pk(p2, p3);
            ull qA = pk(q0, q1), qB = pk(q2, q3);
#pragma unroll
            for (int r = 0; r < TB; r++) {
                ulonglong2 x = outU[r * 128 + i4];             // broadcast
                fma2(acc0[r], x.x, pA); fma2(acc0[r], x.y, pB);
                fma2(acc1[r], x.x, qA); fma2(acc1[r], x.y, qB);
            }
        }
        float bb0 = fcb[t], bb1 = fcb[t + 256];
#pragma unroll
        for (int r = 0; r < TB; r++) {
            float2 f0 = up(acc0[r]), f1 = up(acc1[r]);
            float v0 = f0.x + f0.y + bb0; v0 = (v0 > 0.f) ? v0 : 0.2f * v0;
            float v1 = f1.x + f1.y + bb1; v1 = (v1 > 0.f) ? v1 : 0.2f * v1;
            ln_s[r * DM + t]       = v0;
            ln_s[r * DM + t + 256] = v1;
        }
    }
    __syncthreads();

    // Phase 4: residual (+q_in) + layernorm, in place. Warp w -> row w.
    {
        int w = t >> 5, l = t & 31;
        int row = w;
        int gb = b0 + row;
        float y[16];
        float sum = 0.f, sumsq = 0.f;
#pragma unroll
        for (int e = 0; e < 16; e++) {
            int j = l + e * 32;
            float q;
            if (j < 128)       q = src_s[row * DK + j];
            else if (j < 256)  q = 0.f;
            else if (j < 384)  q = srct[gb * DK + (j - 256)];
            else               q = srcp[gb * DK + (j - 384)];
            float v = ln_s[row * DM + j] + q;
            y[e] = v; sum += v; sumsq += v * v;
        }
#pragma unroll
        for (int o = 16; o > 0; o >>= 1) {
            sum   += __shfl_xor_sync(0xffffffffu, sum, o);
            sumsq += __shfl_xor_sync(0xffffffffu, sumsq, o);
        }
        float mu  = sum * (1.f / 512.f);
        float var = sumsq * (1.f / 512.f) - mu * mu;
        float inv = rsqrtf(var + 1e-5f);
#pragma unroll
        for (int e = 0; e < 16; e++) {
            int j = l + e * 32;
            ln_s[row * DM + j] = (y[e] - mu) * inv * lng[j] + lnb[j];
        }
    }
    __syncthreads();

    int kh = hb;

    // Phase 5: fc1 (K=640 split 2 ways) + relu -> h1_s
    {
        ull a1[TB];
#pragma unroll
        for (int r = 0; r < TB; r++) a1[r] = 0;
        const float* wcol = fc1w + d;
        int i40 = kh * 64;
#pragma unroll 2
        for (int i4 = i40; i4 < i40 + 64; i4++) {
            int j = i4 * 4;
            float w0 = wcol[(j + 0) * DK], w1 = wcol[(j + 1) * DK];
            float w2 = wcol[(j + 2) * DK], w3 = wcol[(j + 3) * DK];
            ull wA = pk(w0, w1), wB = pk(w2, w3);
#pragma unroll
            for (int r = 0; r < TB; r++) {
                ulonglong2 x = lnU[r * 128 + i4];              // broadcast
                fma2(a1[r], x.x, wA); fma2(a1[r], x.y, wB);
            }
        }
        int j40 = kh * 16;
#pragma unroll 2
        for (int j4 = j40; j4 < j40 + 16; j4++) {
            int j = j4 * 4;
            float w0 = wcol[(DM + j + 0) * DK], w1 = wcol[(DM + j + 1) * DK];
            float w2 = wcol[(DM + j + 2) * DK], w3 = wcol[(DM + j + 3) * DK];
            ull wA = pk(w0, w1), wB = pk(w2, w3);
#pragma unroll
            for (int r = 0; r < TB; r++) {
                ulonglong2 x = srcU[r * 32 + j4];              // broadcast
                fma2(a1[r], x.x, wA); fma2(a1[r], x.y, wB);
            }
        }
        if (kh == 1) {
#pragma unroll
            for (int r = 0; r < TB; r++) {
                float2 f = up(a1[r]);
                part[d * 9 + r] = f.x + f.y;
            }
        }
        __syncthreads();
        if (kh == 0) {
            float bb = fc1b[d];
#pragma unroll
            for (int r = 0; r < TB; r++) {
                float2 f = up(a1[r]);
                h1_s[r * DK + d] = fmaxf(f.x + f.y + part[d * 9 + r] + bb, 0.f);
            }
        }
        __syncthreads();
    }

    // Phase 6: fc2 (K=128 split 2 ways) -> z
    {
        ull a2[TB];
#pragma unroll
        for (int r = 0; r < TB; r++) a2[r] = 0;
        const float* wcol = fc2w + d;
        int j40 = kh * 16;
#pragma unroll 2
        for (int j4 = j40; j4 < j40 + 16; j4++) {
            int j = j4 * 4;
            float w0 = wcol[(j + 0) * DK], w1 = wcol[(j + 1) * DK];
            float w2 = wcol[(j + 2) * DK], w3 = wcol[(j + 3) * DK];
            ull wA = pk(w0, w1), wB = pk(w2, w3);
#pragma unroll
            for (int r = 0; r < TB; r++) {
                ulonglong2 x = h1U[r * 32 + j4];               // broadcast
                fma2(a2[r], x.x, wA); fma2(a2[r], x.y, wB);
            }
        }
        if (kh == 1) {
#pragma unroll
            for (int r = 0; r < TB; r++) {
                float2 f = up(a2[r]);
                part[d * 9 + r] = f.x + f.y;
            }
        }
        __syncthreads();
        if (kh == 0) {
            float bb = fc2b[d];
#pragma unroll
            for (int r = 0; r < TB; r++) {
                float2 f = up(a2[r]);
                zout[(size_t)(b0 + r) * DK + d] = f.x + f.y + part[d * 9 + r] + bb;
            }
        }
    }
}

// ---------------------------------------------------------------------------
extern "C" void kernel_launch(void* const* d_in, const int* in_sizes, int n_in,
                              void* d_out, int out_size) {
    (void)in_sizes; (void)n_in; (void)out_size;
    const float* src   = (const float*)d_in[0];
    const float* src_t = (const float*)d_in[1];
    const float* src_p = (const float*)d_in[2];
    const float* seq   = (const float*)d_in[3];
    const float* seq_t = (const float*)d_in[4];
    const float* seq_e = (const float*)d_in[5];
    const float* seq_p = (const float*)d_in[6];
    const int*   mask  = (const int*)d_in[7];
    const float* Wq    = (const float*)d_in[8];
    const float* Wk    = (const float*)d_in[9];
    const float* Wv    = (const float*)d_in[10];
    const float* w_map = (const float*)d_in[11];
    const float* fc_w  = (const float*)d_in[12];
    const float* fc_b  = (const float*)d_in[13];
    const float* ln_g  = (const float*)d_in[14];
    const float* ln_b  = (const float*)d_in[15];
    const float* fc1_w = (const float*)d_in[16];
    const float* fc1_b = (const float*)d_in[17];
    const float* fc2_w = (const float*)d_in[18];
    const float* fc2_b = (const float*)d_in[19];

    float* out      = (float*)d_out;
    float* z_out    = out;                 // [2048,1,128]
    float* attn_out = out + NB * DK;       // [2048,4,1,64]

    fold_kernel<<<DM, 128>>>(Wq, Wk, w_map);
    score_kernel<<<NB, 256>>>(src, src_t, src_p, seq, seq_e, seq_t, seq_p,
                              mask, attn_out);

    const int smem2 = SM_TOTF * (int)sizeof(float);
    cudaFuncSetAttribute(tail_kernel, cudaFuncAttributeMaxDynamicSharedMemorySize, smem2);
    tail_kernel<<<NB / TB, 256, smem2>>>(src, src_t, src_p,
                                         seq, seq_e, seq_t, seq_p,
                                         Wv, fc_w, fc_b, ln_g, ln_b,
                                         fc1_w, fc1_b, fc2_w, fc2_b, z_out);
}